// round 12
// baseline (speedup 1.0000x reference)
#include <cuda_runtime.h>
#include <cuda_fp16.h>
#include <math.h>

#define N_EDGES_C 100000
#define N_NODES_C 20000
#define NTILES    (N_EDGES_C / 16)   // 6250
#define GRID_C    148
#define STATIC_TILES (GRID_C * 16)   // 2368 — first tile per warp is static
#define FEAT_BLOCKS 1250             // 16 nodes per block
#define H_BLOCKS    782              // 128 edges per block (ceil)

// e3nn constants: C0=C1=C2=1/sqrt(48), C3=0.25
#define C0F 0.14433756729740643f
#define C1F 0.14433756729740643f
#define C2F 0.14433756729740643f
#define C3F 0.25f

// ---- smem layout (bytes) ----
#define BG_OFF 0                      // uint4[32*3*32] = 49152
#define BP_OFF 49152                  // uint4[16*2*32] = 16384
#define BQ_OFF 65536                  // uint4[16*1*32] =  8192
#define WS_OFF 73728
#define WS_STRIDE 9856                // per warp
#define BUF_STRIDE 4608               // two staging buffers per warp
// within a buffer:
#define HD_B 0        // h dup-packed: 16 edges x 80B stride (64B used)
#define S1_B 1280     // s1 fp16 pairs: 16 x 80B stride (64B used)
#define V1_B 2560     // v1T fp16: 16 x 112B stride (96B used: [i<3][u<16])
#define SV_B 4352     // float4[16] = {s2, v2x, v2y, v2z}
// single-buffered per warp:
#define BH_B 9216     // b fp16: 16 x 40B stride (32B used)
#define SMEM_TOTAL (WS_OFF + 16 * WS_STRIDE)   // 231,424

__device__ uint4 g_feat[N_NODES_C * 10];   // [node]{32h s1 | 48h v1T}  160B/row
__device__ uint4 g_hdup[N_EDGES_C * 4];    // [edge] 16 x f16x2(dup)     64B/row
__device__ unsigned int g_ticket;

__device__ __forceinline__ unsigned packh(float lo, float hi) {
    unsigned r;
    asm("cvt.rn.f16x2.f32 %0, %1, %2;" : "=r"(r) : "f"(hi), "f"(lo));
    return r;
}
__device__ __forceinline__ unsigned h2u(__half2 h) { return *(unsigned*)&h; }
__device__ __forceinline__ __half2  u2h(unsigned u) { return *(__half2*)&u; }

__device__ __forceinline__ void cpa16(unsigned dst_s, const void* src) {
    asm volatile("cp.async.cg.shared.global [%0], [%1], 16;" :: "r"(dst_s), "l"(src));
}
__device__ __forceinline__ void cpa_commit() {
    asm volatile("cp.async.commit_group;");
}
__device__ __forceinline__ void cpa_wait0() {
    asm volatile("cp.async.wait_group 0;");
}

// NOTE: not volatile — pure register op; lets the compiler interleave B loads
// with the MMA dependency chains.
__device__ __forceinline__ void mma16816(float* d,
    unsigned a0, unsigned a1, unsigned a2, unsigned a3,
    unsigned b0, unsigned b1)
{
    asm("mma.sync.aligned.m16n8k16.row.col.f32.f16.f16.f32 "
        "{%0,%1,%2,%3},{%4,%5,%6,%7},{%8,%9},{%0,%1,%2,%3};"
        : "+f"(d[0]), "+f"(d[1]), "+f"(d[2]), "+f"(d[3])
        : "r"(a0), "r"(a1), "r"(a2), "r"(a3), "r"(b0), "r"(b1));
}

// ========== pre-kernel: feature convert (coalesced) + h precompute ==========
__global__ __launch_bounds__(128)
void pre_k(const float* __restrict__ feature,
           const float* __restrict__ ele,
           const float* __restrict__ fw1,
           float silu_c)
{
    __shared__ float sm[16 * 84];     // feature rows, padded stride
    __shared__ float se[128 * 11];    // ele rows, padded stride
    __shared__ float sw1[160];

    const int tid = threadIdx.x;
    if (blockIdx.x == 0 && tid == 0) g_ticket = STATIC_TILES;  // atomics start past static tiles

    if (blockIdx.x < FEAT_BLOCKS) {
        // ---- 16 nodes: coalesced 320x LDG.128 into smem, then pack ----
        const int n0 = blockIdx.x * 16;
        const float4* src = (const float4*)(feature + (size_t)n0 * 80);
        #pragma unroll
        for (int it = 0; it < 3; it++) {
            int i = it * 128 + tid;
            if (i < 320) {
                float4 v = src[i];
                int r = i / 20, c = i % 20;
                ((float4*)(sm + r * 84))[c] = v;
            }
        }
        __syncthreads();

        const int n = tid >> 3, part = tid & 7;
        const float* fr = sm + n * 84;
        if (part < 4) {
            unsigned o[4];
            #pragma unroll
            for (int q = 0; q < 4; q++)
                o[q] = packh(fr[part*8 + 2*q], fr[part*8 + 2*q + 1]);
            g_feat[(size_t)(n0 + n) * 10 + part] = make_uint4(o[0], o[1], o[2], o[3]);
        } else if (part < 7) {
            int i = part - 4;
            unsigned o[8];
            #pragma unroll
            for (int q = 0; q < 8; q++)
                o[q] = packh(fr[32 + (2*q)*3 + i], fr[32 + (2*q+1)*3 + i]);
            uint4* dst = g_feat + (size_t)(n0 + n) * 10 + 4 + i * 2;
            dst[0] = make_uint4(o[0], o[1], o[2], o[3]);
            dst[1] = make_uint4(o[4], o[5], o[6], o[7]);
        }
    } else {
        // ---- 128 edges: h = SILU_C * silu(ele @ W1n) ----
        const int e0 = (blockIdx.x - FEAT_BLOCKS) * 128;
        #pragma unroll
        for (int it = 0; it < 10; it++) {
            int i = it * 128 + tid;               // 1280 floats
            int gidx = e0 * 10 + i;
            float v = (gidx < N_EDGES_C * 10) ? ele[gidx] : 0.f;
            se[(i / 10) * 11 + (i % 10)] = v;
        }
        {
            const float inb = 0.31622776601683794f; // 1/sqrt(10)
            for (int i = tid; i < 160; i += 128)
                sw1[i] = fw1[i] * inb;
        }
        __syncthreads();

        const int e = e0 + tid;
        if (e < N_EDGES_C) {
            const float* x = se + tid * 11;
            unsigned hv[16];
            #pragma unroll
            for (int k = 0; k < 16; k++) {
                float a = 0.f;
                #pragma unroll
                for (int j = 0; j < 10; j++) a = fmaf(x[j], sw1[j*16 + k], a);
                float sg = 1.0f / (1.0f + __expf(-a));
                hv[k] = h2u(__float2half2_rn(silu_c * a * sg));
            }
            uint4* o = g_hdup + (size_t)e * 4;
            #pragma unroll
            for (int q = 0; q < 4; q++)
                o[q] = make_uint4(hv[4*q], hv[4*q+1], hv[4*q+2], hv[4*q+3]);
        }
    }

    // PDL: release the dependent launch as this block retires. All g_feat/
    // g_hdup/g_ticket stores precede this in program order; the consumer's
    // cudaGridDependencySynchronize() still guarantees full visibility.
    cudaTriggerProgrammaticLaunchCompletion();
}

// ============================== main kernel ====================================
__global__ __launch_bounds__(512, 1)
void tp_mma6_kernel(const int*   __restrict__ edge,
                    const float* __restrict__ esh,
                    const float* __restrict__ fw2,
                    float*       __restrict__ out)
{
    extern __shared__ char smem[];
    uint4* BG4 = (uint4*)(smem + BG_OFF);
    uint4* BP4 = (uint4*)(smem + BP_OFF);
    uint4* BQ4 = (uint4*)(smem + BQ_OFF);

    const int tid  = threadIdx.x;
    const int lane = tid & 31;
    const int warp = tid >> 5;
    const int gq   = lane >> 2;
    const int t    = lane & 3;

    // ---- stage fragment-major B (fp16, uint4) — independent of pre_k output --
    for (int i = tid; i < 4608; i += 512) {
        int li = i & 31, gg = li >> 2, tt = li & 3;
        float va[4], vb[4];
        if (i < 3072) {                 // BG: mm = kc*3 + p (W0|W1, K=512, N=48)
            int mm = i >> 5;
            int kc = mm / 3, p = mm % 3;
            int k0 = kc * 16;
            int c0 = (2 * p) * 8 + gg, c1 = c0 + 8;
            int ks[4] = {k0 + 2*tt, k0 + 2*tt + 1, k0 + 2*tt + 8, k0 + 2*tt + 9};
            #pragma unroll
            for (int j = 0; j < 4; j++) {
                int k = ks[j], kh = k >> 5, u = k & 31;
                va[j] = 0.25f * (c0 < 32 ? fw2[kh*2304 + u*32 + c0]
                                         : fw2[kh*2304 + 1024 + u*16 + (c0-32)]);
                vb[j] = 0.25f * (c1 < 32 ? fw2[kh*2304 + u*32 + c1]
                                         : fw2[kh*2304 + 1024 + u*16 + (c1-32)]);
            }
            BG4[mm * 32 + li] = make_uint4(packh(va[0],va[1]), packh(va[2],va[3]),
                                           packh(vb[0],vb[1]), packh(vb[2],vb[3]));
        } else if (i < 4096) {          // BP: W3, K=256, N=32
            int ii = i - 3072;
            int mm = ii >> 5;
            int kc = mm >> 1, p = mm & 1;
            int k0 = kc * 16;
            int c0 = (2 * p) * 8 + gg, c1 = c0 + 8;
            int ks[4] = {k0 + 2*tt, k0 + 2*tt + 1, k0 + 2*tt + 8, k0 + 2*tt + 9};
            #pragma unroll
            for (int j = 0; j < 4; j++) {
                int k = ks[j], kh = k >> 4, u = k & 15;
                va[j] = 0.25f * fw2[kh*2304 + 1792 + u*32 + c0];
                vb[j] = 0.25f * fw2[kh*2304 + 1792 + u*32 + c1];
            }
            BP4[ii] = make_uint4(packh(va[0],va[1]), packh(va[2],va[3]),
                                 packh(vb[0],vb[1]), packh(vb[2],vb[3]));
        } else {                        // BQ: W2, K=256, N=16
            int ii = i - 4096;
            int kc = ii >> 5;
            int k0 = kc * 16;
            int c0 = gg, c1 = 8 + gg;
            int ks[4] = {k0 + 2*tt, k0 + 2*tt + 1, k0 + 2*tt + 8, k0 + 2*tt + 9};
            #pragma unroll
            for (int j = 0; j < 4; j++) {
                int k = ks[j], kh = k >> 4, u = k & 15;
                va[j] = 0.25f * fw2[kh*2304 + 1536 + u*16 + c0];
                vb[j] = 0.25f * fw2[kh*2304 + 1536 + u*16 + c1];
            }
            BQ4[ii] = make_uint4(packh(va[0],va[1]), packh(va[2],va[3]),
                                 packh(vb[0],vb[1]), packh(vb[2],vb[3]));
        }
    }
    __syncthreads();

    // ---- PDL join: wait for pre_k's g_feat/g_hdup/g_ticket to be visible ----
    cudaGridDependencySynchronize();

    char*    wsb   = smem + WS_OFF + warp * WS_STRIDE;
    unsigned ws_s  = (unsigned)__cvta_generic_to_shared(wsb);
    const uint4* BGl = BG4 + lane;
    const uint4* BPl = BP4 + lane;
    const uint4* BQl = BQ4 + lane;
    const unsigned* BHu = (const unsigned*)(wsb + BH_B);

    #define STAGE_H(bufofs, e0v) do {                                            \
        const char* _src = (const char*)g_hdup + (size_t)(e0v) * 64;             \
        _Pragma("unroll")                                                        \
        for (int _it = 0; _it < 2; _it++) {                                      \
            int _idx = _it * 32 + lane;                                          \
            int _m = _idx >> 2, _j = _idx & 3;                                   \
            cpa16(ws_s + (bufofs) + HD_B + _m * 80 + _j * 16, _src + _idx * 16); \
        } } while (0)

    #define STAGE_SV(bufofs, dregv) do {                                         \
        _Pragma("unroll")                                                        \
        for (int _it = 0; _it < 5; _it++) {                                      \
            int _idx = _it * 32 + lane;                                          \
            if (_idx < 64) {                                                     \
                int _m = _idx >> 2, _j = _idx & 3;                               \
                int _d = __shfl_sync(0xFFFFFFFFu, (dregv), _m);                  \
                cpa16(ws_s + (bufofs) + S1_B + _m * 80 + _j * 16,                \
                      (const char*)g_feat + (size_t)_d * 160 + _j * 16);         \
            } else {                                                             \
                int _v = _idx - 64;                                              \
                int _m = _v / 6, _j = _v - _m * 6;                               \
                int _d = __shfl_sync(0xFFFFFFFFu, (dregv), _m);                  \
                cpa16(ws_s + (bufofs) + V1_B + _m * 112 + _j * 16,               \
                      (const char*)g_feat + (size_t)_d * 160 + 64 + _j * 16);    \
            }                                                                    \
        } } while (0)

    #define PREFIX(bufofs, eshvv) do {                                           \
        char* _nb = wsb + (bufofs);                                              \
        if (lane < 16) ((float4*)(_nb + SV_B))[lane] = (eshvv);                  \
        __syncwarp();                                                            \
        {                                                                        \
            int _m = lane >> 1, _ub = (lane & 1) * 8;                            \
            float4 _sv = ((const float4*)(_nb + SV_B))[_m];                      \
            const __half* _v1h = (const __half*)(_nb + V1_B) + _m * 56;          \
            __half* _bh = (__half*)(wsb + BH_B) + _m * 20;                       \
            _Pragma("unroll")                                                    \
            for (int _j = 0; _j < 8; _j++) {                                     \
                int _u = _ub + _j;                                               \
                float _vx = __half2float(_v1h[_u]);                              \
                float _vy = __half2float(_v1h[16 + _u]);                         \
                float _vz = __half2float(_v1h[32 + _u]);                         \
                _bh[_u] = __float2half(fmaf(_vx, _sv.y,                          \
                                       fmaf(_vy, _sv.z, _vz * _sv.w)));          \
            }                                                                    \
        }                                                                        \
        __syncwarp();                                                            \
    } while (0)

    // ---------------- bootstrap first tile (STATIC — no atomic) ----------------
    unsigned cur = (unsigned)(blockIdx.x * 16 + warp);   // < 2368 < NTILES always

    int buf = 0;
    int e0 = (int)cur * 16;
    {
        STAGE_H(0, e0);
        float4 eshv = make_float4(0.f, 0.f, 0.f, 0.f);
        int dreg = 0;
        if (lane < 16) {
            dreg = edge[N_EDGES_C + e0 + lane];
            eshv = ((const float4*)esh)[e0 + lane];
        }
        STAGE_SV(0, dreg);
        cpa_commit(); cpa_wait0(); __syncwarp();
        PREFIX(0, eshv);
    }

    // ---------------- pipelined tile loop ----------------
    for (;;) {
        const int bofs  = buf * BUF_STRIDE;
        const int nbofs = (buf ^ 1) * BUF_STRIDE;
        const char* cb  = wsb + bofs;
        const unsigned* HD0 = (const unsigned*)(cb + HD_B) + gq * 20;
        const unsigned* HD1 = (const unsigned*)(cb + HD_B) + (gq + 8) * 20;
        const unsigned* S10 = (const unsigned*)(cb + S1_B) + gq * 20;
        const unsigned* S11 = (const unsigned*)(cb + S1_B) + (gq + 8) * 20;
        const unsigned* V1u = (const unsigned*)(cb + V1_B);
        const float4*   SV  = (const float4*)(cb + SV_B);

        // ---- register-resident A operands for this tile (loaded ONCE) ----
        unsigned hA[16], hB[16];
        #pragma unroll
        for (int k = 0; k < 16; k++) { hA[k] = HD0[k]; hB[k] = HD1[k]; }
        unsigned sAr[4], sBr[4];
        sAr[0] = S10[t];     sAr[1] = S10[t + 4];
        sAr[2] = S10[8 + t]; sAr[3] = S10[12 + t];
        sBr[0] = S11[t];     sBr[1] = S11[t + 4];
        sBr[2] = S11[8 + t]; sBr[3] = S11[12 + t];

        // ---- fetch next ticket; stage h/dst/esh for it ----
        unsigned nxt;
        if (lane == 0) nxt = atomicAdd(&g_ticket, 1u);
        nxt = __shfl_sync(0xFFFFFFFFu, nxt, 0);
        const bool hn = (nxt < NTILES);
        float4 eshn = make_float4(0.f, 0.f, 0.f, 0.f);
        int dn = 0;
        if (hn) {
            int en = (int)nxt * 16;
            STAGE_H(nbofs, en);
            if (lane < 16) {
                dn   = edge[N_EDGES_C + en + lane];
                eshn = ((const float4*)esh)[en + lane];
            }
        }

        // ================ GEMM 1: g = h(x)s1, N=48 (R0|R1) ================
        float ag[6][4];
        #pragma unroll
        for (int nb = 0; nb < 6; nb++) { ag[nb][0]=0.f; ag[nb][1]=0.f; ag[nb][2]=0.f; ag[nb][3]=0.f; }

        // rotating B prefetch: bb holds kc's three blocks
        uint4 bb0 = BGl[0], bb1 = BGl[32], bb2 = BGl[64];
        #pragma unroll
        for (int kh = 0; kh < 16; kh++) {
            __half2 h0 = u2h(hA[kh]), h1 = u2h(hB[kh]);
            #pragma unroll
            for (int p = 0; p < 2; p++) {
                int kc = kh * 2 + p;
                __half2 xa = u2h(sAr[p*2+0]), xb = u2h(sAr[p*2+1]);
                __half2 ya = u2h(sBr[p*2+0]), yb = u2h(sBr[p*2+1]);
                unsigned a0 = h2u(__hmul2(h0, xa)), a1 = h2u(__hmul2(h1, ya));
                unsigned a2 = h2u(__hmul2(h0, xb)), a3 = h2u(__hmul2(h1, yb));
                mma16816(ag[0], a0, a1, a2, a3, bb0.x, bb0.y);
                mma16816(ag[1], a0, a1, a2, a3, bb0.z, bb0.w);
                mma16816(ag[2], a0, a1, a2, a3, bb1.x, bb1.y);
                mma16816(ag[3], a0, a1, a2, a3, bb1.z, bb1.w);
                mma16816(ag[4], a0, a1, a2, a3, bb2.x, bb2.y);
                mma16816(ag[5], a0, a1, a2, a3, bb2.z, bb2.w);
                if (kc < 31) {
                    bb0 = BGl[(kc+1) * 96];
                    bb1 = BGl[(kc+1) * 96 + 32];
                    bb2 = BGl[(kc+1) * 96 + 64];
                }
            }
        }

        // ---- stage dst-dependent s1/v1T for next tile ----
        if (hn) STAGE_SV(nbofs, dn);
        cpa_commit();

        // ================ GEMM 2: p = h(x)b, N=32 (R3) ================
        unsigned bAr[2], bBr[2];
        bAr[0] = BHu[gq*10 + t];       bAr[1] = BHu[gq*10 + t + 4];
        bBr[0] = BHu[(gq+8)*10 + t];   bBr[1] = BHu[(gq+8)*10 + t + 4];

        float ap[4][4];
        #pragma unroll
        for (int nb = 0; nb < 4; nb++) { ap[nb][0]=0.f; ap[nb][1]=0.f; ap[nb][2]=0.f; ap[nb][3]=0.f; }

        #pragma unroll
        for (int kc = 0; kc < 16; kc++) {
            __half2 h0 = u2h(hA[kc]), h1 = u2h(hB[kc]);
            __half2 xa = u2h(bAr[0]), xb = u2h(bAr[1]);
            __half2 ya = u2h(bBr[0]), yb = u2h(bBr[1]);
            unsigned a0 = h2u(__hmul2(h0, xa)), a1 = h2u(__hmul2(h1, ya));
            unsigned a2 = h2u(__hmul2(h0, xb)), a3 = h2u(__hmul2(h1, yb));
            #pragma unroll
            for (int p = 0; p < 2; p++) {
                uint4 bb = BPl[kc * 64 + p * 32];
                mma16816(ap[2*p],   a0, a1, a2, a3, bb.x, bb.y);
                mma16816(ap[2*p+1], a0, a1, a2, a3, bb.z, bb.w);
            }
        }

        // ---- epilogue 1: out_s = C0*s2*R0 + C3*R3 ----
        {
            float4 sv0 = SV[gq], sv1 = SV[gq + 8];
            float* row0 = out + (size_t)(e0 + gq) * 80;
            float* row1 = out + (size_t)(e0 + gq + 8) * 80;
            #pragma unroll
            for (int nb = 0; nb < 4; nb++) {
                int w = nb * 8 + 2 * t;
                float2 o0, o1;
                o0.x = fmaf(C0F * sv0.x, ag[nb][0], C3F * ap[nb][0]);
                o0.y = fmaf(C0F * sv0.x, ag[nb][1], C3F * ap[nb][1]);
                o1.x = fmaf(C0F * sv1.x, ag[nb][2], C3F * ap[nb][2]);
                o1.y = fmaf(C0F * sv1.x, ag[nb][3], C3F * ap[nb][3]);
                *(float2*)(row0 + w) = o0;
                *(float2*)(row1 + w) = o1;
            }
        }

        // ================ GEMM 3: q_i = h(x)v1_i, N=16 each (R2i) ================
        unsigned vAr[3][2], vBr[3][2];
        #pragma unroll
        for (int i = 0; i < 3; i++) {
            vAr[i][0] = V1u[gq*28 + i*8 + t];     vAr[i][1] = V1u[gq*28 + i*8 + t + 4];
            vBr[i][0] = V1u[(gq+8)*28 + i*8 + t]; vBr[i][1] = V1u[(gq+8)*28 + i*8 + t + 4];
        }

        float aq[3][2][4];
        #pragma unroll
        for (int i = 0; i < 3; i++)
            #pragma unroll
            for (int nb = 0; nb < 2; nb++) { aq[i][nb][0]=0.f; aq[i][nb][1]=0.f; aq[i][nb][2]=0.f; aq[i][nb][3]=0.f; }

        #pragma unroll
        for (int kc = 0; kc < 16; kc++) {
            __half2 h0 = u2h(hA[kc]), h1 = u2h(hB[kc]);
            uint4 bb = BQl[kc * 32];
            #pragma unroll
            for (int i = 0; i < 3; i++) {
                __half2 xa = u2h(vAr[i][0]), xb = u2h(vAr[i][1]);
                __half2 ya = u2h(vBr[i][0]), yb = u2h(vBr[i][1]);
                unsigned a0 = h2u(__hmul2(h0, xa)), a1 = h2u(__hmul2(h1, ya));
                unsigned a2 = h2u(__hmul2(h0, xb)), a3 = h2u(__hmul2(h1, yb));
                mma16816(aq[i][0], a0, a1, a2, a3, bb.x, bb.y);
                mma16816(aq[i][1], a0, a1, a2, a3, bb.z, bb.w);
            }
        }

        // ---- epilogue 2: out_v[w][i] = C1*v2[i]*R1[w] + C2*s2*R2i[w] ----
        {
            float4 sv0 = SV[gq], sv1 = SV[gq + 8];
            float* row0 = out + (size_t)(e0 + gq) * 80 + 32;
            float* row1 = out + (size_t)(e0 + gq + 8) * 80 + 32;
            #pragma unroll
            for (int nbv = 0; nbv < 2; nbv++) {
                int w = nbv * 8 + 2 * t;
                float R1a0 = ag[4 + nbv][0], R1b0 = ag[4 + nbv][1];
                float R1a1 = ag[4 + nbv][2], R1b1 = ag[4 + nbv][3];
                float v20[3] = {sv0.y, sv0.z, sv0.w};
                float v21[3] = {sv1.y, sv1.z, sv1.w};
                float o0[6], o1[6];
                #pragma unroll
                for (int i = 0; i < 3; i++) {
                    o0[i]     = fmaf(C1F * v20[i], R1a0, C2F * sv0.x * aq[i][nbv][0]);
                    o0[3 + i] = fmaf(C1F * v20[i], R1b0, C2F * sv0.x * aq[i][nbv][1]);
                    o1[i]     = fmaf(C1F * v21[i], R1a1, C2F * sv1.x * aq[i][nbv][2]);
                    o1[3 + i] = fmaf(C1F * v21[i], R1b1, C2F * sv1.x * aq[i][nbv][3]);
                }
                #pragma unroll
                for (int j = 0; j < 3; j++) {
                    *(float2*)(row0 + 3 * w + 2 * j) = make_float2(o0[2*j], o0[2*j+1]);
                    *(float2*)(row1 + 3 * w + 2 * j) = make_float2(o1[2*j], o1[2*j+1]);
                }
            }
        }

        if (!hn) break;
        // ---- retire next tile's staged data, run its short prefix ----
        cpa_wait0(); __syncwarp();
        PREFIX(nbofs, eshn);
        buf ^= 1;
        e0 = (int)nxt * 16;
    }
    #undef STAGE_H
    #undef STAGE_SV
    #undef PREFIX
}

// Host-side exact replication of the reference silu normalization constant.
static float compute_silu_c()
{
    const int N = 200001;
    const double dx = 24.0 / 200000.0;
    const double inv_sqrt_2pi = 0.3989422804014326779;
    double acc = 0.0, prev = 0.0;
    for (int i = 0; i < N; i++) {
        double x = -12.0 + dx * (double)i;
        double pdf = exp(-0.5 * x * x) * inv_sqrt_2pi;
        double s = x / (1.0 + exp(-x));
        double y = s * s * pdf;
        if (i > 0) acc += 0.5 * (y + prev) * dx;
        prev = y;
    }
    return (float)(1.0 / sqrt(acc));
}

extern "C" void kernel_launch(void* const* d_in, const int* in_sizes, int n_in,
                              void* d_out, int out_size)
{
    const float* feature = (const float*)d_in[0];
    const int*   edge    = (const int*)  d_in[1];
    const float* ele     = (const float*)d_in[2];
    const float* esh     = (const float*)d_in[3];
    const float* fw1     = (const float*)d_in[4];
    const float* fw2     = (const float*)d_in[5];
    float* out = (float*)d_out;

    float silu_c = compute_silu_c();

    cudaFuncSetAttribute(tp_mma6_kernel,
                         cudaFuncAttributeMaxDynamicSharedMemorySize, SMEM_TOTAL);

    pre_k<<<FEAT_BLOCKS + H_BLOCKS, 128>>>(feature, ele, fw1, silu_c);

    // PDL launch: main kernel starts while pre_k drains; its B-staging prologue
    // overlaps pre_k, and cudaGridDependencySynchronize() gates the tile loop.
    cudaLaunchConfig_t cfg = {};
    cfg.gridDim = dim3(GRID_C, 1, 1);
    cfg.blockDim = dim3(512, 1, 1);
    cfg.dynamicSmemBytes = SMEM_TOTAL;
    cfg.stream = 0;
    cudaLaunchAttribute attrs[1];
    attrs[0].id = cudaLaunchAttributeProgrammaticStreamSerialization;
    attrs[0].val.programmaticStreamSerializationAllowed = 1;
    cfg.attrs = attrs;
    cfg.numAttrs = 1;
    cudaError_t err = cudaLaunchKernelEx(&cfg, tp_mma6_kernel, edge, esh, fw2, out);
    if (err != cudaSuccess) {
        // Fallback: plain serialized launch (gridDepSync degenerates to no-op).
        tp_mma6_kernel<<<GRID_C, 512, SMEM_TOTAL>>>(edge, esh, fw2, out);
    }
}

// round 13
// speedup vs baseline: 1.0392x; 1.0392x over previous
#include <cuda_runtime.h>
#include <cuda_fp16.h>
#include <math.h>

#define N_EDGES_C 100000
#define N_NODES_C 20000
#define NTILES    (N_EDGES_C / 16)   // 6250
#define GRID_C    148
#define STATIC_TILES (GRID_C * 16)   // 2368 — first tile per warp is static
#define FEAT_BLOCKS 1250             // 16 nodes per block
#define H_BLOCKS    782              // 128 edges per block (ceil)

// e3nn constants: C0=C1=C2=1/sqrt(48), C3=0.25
#define C0F 0.14433756729740643f
#define C1F 0.14433756729740643f
#define C2F 0.14433756729740643f
#define C3F 0.25f

// ---- smem layout (bytes) ----
#define BG_OFF 0                      // uint4[32*3*32] = 49152
#define BP_OFF 49152                  // uint4[16*2*32] = 16384
#define BQ_OFF 65536                  // uint4[16*1*32] =  8192
#define WS_OFF 73728
#define WS_STRIDE 9856                // per warp
#define BUF_STRIDE 4608               // two staging buffers per warp
// within a buffer:
#define HD_B 0        // h dup-packed: 16 edges x 80B stride (64B used)
#define S1_B 1280     // s1 fp16 pairs: 16 x 80B stride (64B used)
#define V1_B 2560     // v1T fp16: 16 x 112B stride (96B used: [i<3][u<16])
#define SV_B 4352     // float4[16] = {s2, v2x, v2y, v2z}
// single-buffered per warp:
#define BH_B 9216     // b fp16: 16 x 40B stride (32B used)
#define SMEM_TOTAL (WS_OFF + 16 * WS_STRIDE)   // 231,424

__device__ uint4 g_feat[N_NODES_C * 10];   // [node]{32h s1 | 48h v1T}  160B/row
__device__ uint4 g_hdup[N_EDGES_C * 4];    // [edge] 16 x f16x2(dup)     64B/row
__device__ unsigned int g_ticket;

__device__ __forceinline__ unsigned packh(float lo, float hi) {
    unsigned r;
    asm("cvt.rn.f16x2.f32 %0, %1, %2;" : "=r"(r) : "f"(hi), "f"(lo));
    return r;
}
__device__ __forceinline__ unsigned h2u(__half2 h) { return *(unsigned*)&h; }
__device__ __forceinline__ __half2  u2h(unsigned u) { return *(__half2*)&u; }

__device__ __forceinline__ void cpa16(unsigned dst_s, const void* src) {
    asm volatile("cp.async.cg.shared.global [%0], [%1], 16;" :: "r"(dst_s), "l"(src));
}
__device__ __forceinline__ void cpa_commit() {
    asm volatile("cp.async.commit_group;");
}
__device__ __forceinline__ void cpa_wait0() {
    asm volatile("cp.async.wait_group 0;");
}

// NOTE: not volatile — pure register op; lets the compiler interleave B loads
// with the MMA dependency chains.
__device__ __forceinline__ void mma16816(float* d,
    unsigned a0, unsigned a1, unsigned a2, unsigned a3,
    unsigned b0, unsigned b1)
{
    asm("mma.sync.aligned.m16n8k16.row.col.f32.f16.f16.f32 "
        "{%0,%1,%2,%3},{%4,%5,%6,%7},{%8,%9},{%0,%1,%2,%3};"
        : "+f"(d[0]), "+f"(d[1]), "+f"(d[2]), "+f"(d[3])
        : "r"(a0), "r"(a1), "r"(a2), "r"(a3), "r"(b0), "r"(b1));
}

// ========== pre-kernel: feature convert (coalesced) + h precompute ==========
__global__ __launch_bounds__(128)
void pre_k(const float* __restrict__ feature,
           const float* __restrict__ ele,
           const float* __restrict__ fw1,
           float silu_c)
{
    __shared__ float sm[16 * 84];     // feature rows, padded stride
    __shared__ float se[128 * 11];    // ele rows, padded stride
    __shared__ float sw1[160];

    const int tid = threadIdx.x;
    if (blockIdx.x == 0 && tid == 0) g_ticket = STATIC_TILES;  // atomics start past static tiles

    if (blockIdx.x < FEAT_BLOCKS) {
        // ---- 16 nodes: coalesced 320x LDG.128 into smem, then pack ----
        const int n0 = blockIdx.x * 16;
        const float4* src = (const float4*)(feature + (size_t)n0 * 80);
        #pragma unroll
        for (int it = 0; it < 3; it++) {
            int i = it * 128 + tid;
            if (i < 320) {
                float4 v = src[i];
                int r = i / 20, c = i % 20;
                ((float4*)(sm + r * 84))[c] = v;
            }
        }
        __syncthreads();

        const int n = tid >> 3, part = tid & 7;
        const float* fr = sm + n * 84;
        if (part < 4) {
            unsigned o[4];
            #pragma unroll
            for (int q = 0; q < 4; q++)
                o[q] = packh(fr[part*8 + 2*q], fr[part*8 + 2*q + 1]);
            g_feat[(size_t)(n0 + n) * 10 + part] = make_uint4(o[0], o[1], o[2], o[3]);
        } else if (part < 7) {
            int i = part - 4;
            unsigned o[8];
            #pragma unroll
            for (int q = 0; q < 8; q++)
                o[q] = packh(fr[32 + (2*q)*3 + i], fr[32 + (2*q+1)*3 + i]);
            uint4* dst = g_feat + (size_t)(n0 + n) * 10 + 4 + i * 2;
            dst[0] = make_uint4(o[0], o[1], o[2], o[3]);
            dst[1] = make_uint4(o[4], o[5], o[6], o[7]);
        }
    } else {
        // ---- 128 edges: h = SILU_C * silu(ele @ W1n) ----
        const int e0 = (blockIdx.x - FEAT_BLOCKS) * 128;
        #pragma unroll
        for (int it = 0; it < 10; it++) {
            int i = it * 128 + tid;               // 1280 floats
            int gidx = e0 * 10 + i;
            float v = (gidx < N_EDGES_C * 10) ? ele[gidx] : 0.f;
            se[(i / 10) * 11 + (i % 10)] = v;
        }
        {
            const float inb = 0.31622776601683794f; // 1/sqrt(10)
            for (int i = tid; i < 160; i += 128)
                sw1[i] = fw1[i] * inb;
        }
        __syncthreads();

        const int e = e0 + tid;
        if (e < N_EDGES_C) {
            const float* x = se + tid * 11;
            unsigned hv[16];
            #pragma unroll
            for (int k = 0; k < 16; k++) {
                float a = 0.f;
                #pragma unroll
                for (int j = 0; j < 10; j++) a = fmaf(x[j], sw1[j*16 + k], a);
                float sg = 1.0f / (1.0f + __expf(-a));
                hv[k] = h2u(__float2half2_rn(silu_c * a * sg));
            }
            uint4* o = g_hdup + (size_t)e * 4;
            #pragma unroll
            for (int q = 0; q < 4; q++)
                o[q] = make_uint4(hv[4*q], hv[4*q+1], hv[4*q+2], hv[4*q+3]);
        }
    }

    // PDL: release the dependent launch as this block retires. All g_feat/
    // g_hdup/g_ticket stores precede this in program order; the consumer's
    // cudaGridDependencySynchronize() still guarantees full visibility.
    cudaTriggerProgrammaticLaunchCompletion();
}

// ============================== main kernel ====================================
__global__ __launch_bounds__(512, 1)
void tp_mma6_kernel(const int*   __restrict__ edge,
                    const float* __restrict__ esh,
                    const float* __restrict__ fw2,
                    float*       __restrict__ out)
{
    extern __shared__ char smem[];
    uint4* BG4 = (uint4*)(smem + BG_OFF);
    uint4* BP4 = (uint4*)(smem + BP_OFF);
    uint4* BQ4 = (uint4*)(smem + BQ_OFF);

    const int tid  = threadIdx.x;
    const int lane = tid & 31;
    const int warp = tid >> 5;
    const int gq   = lane >> 2;
    const int t    = lane & 3;

    // ---- stage fragment-major B (fp16, uint4) — independent of pre_k output --
    for (int i = tid; i < 4608; i += 512) {
        int li = i & 31, gg = li >> 2, tt = li & 3;
        float va[4], vb[4];
        if (i < 3072) {                 // BG: mm = kc*3 + p (W0|W1, K=512, N=48)
            int mm = i >> 5;
            int kc = mm / 3, p = mm % 3;
            int k0 = kc * 16;
            int c0 = (2 * p) * 8 + gg, c1 = c0 + 8;
            int ks[4] = {k0 + 2*tt, k0 + 2*tt + 1, k0 + 2*tt + 8, k0 + 2*tt + 9};
            #pragma unroll
            for (int j = 0; j < 4; j++) {
                int k = ks[j], kh = k >> 5, u = k & 31;
                va[j] = 0.25f * (c0 < 32 ? fw2[kh*2304 + u*32 + c0]
                                         : fw2[kh*2304 + 1024 + u*16 + (c0-32)]);
                vb[j] = 0.25f * (c1 < 32 ? fw2[kh*2304 + u*32 + c1]
                                         : fw2[kh*2304 + 1024 + u*16 + (c1-32)]);
            }
            BG4[mm * 32 + li] = make_uint4(packh(va[0],va[1]), packh(va[2],va[3]),
                                           packh(vb[0],vb[1]), packh(vb[2],vb[3]));
        } else if (i < 4096) {          // BP: W3, K=256, N=32
            int ii = i - 3072;
            int mm = ii >> 5;
            int kc = mm >> 1, p = mm & 1;
            int k0 = kc * 16;
            int c0 = (2 * p) * 8 + gg, c1 = c0 + 8;
            int ks[4] = {k0 + 2*tt, k0 + 2*tt + 1, k0 + 2*tt + 8, k0 + 2*tt + 9};
            #pragma unroll
            for (int j = 0; j < 4; j++) {
                int k = ks[j], kh = k >> 4, u = k & 15;
                va[j] = 0.25f * fw2[kh*2304 + 1792 + u*32 + c0];
                vb[j] = 0.25f * fw2[kh*2304 + 1792 + u*32 + c1];
            }
            BP4[ii] = make_uint4(packh(va[0],va[1]), packh(va[2],va[3]),
                                 packh(vb[0],vb[1]), packh(vb[2],vb[3]));
        } else {                        // BQ: W2, K=256, N=16
            int ii = i - 4096;
            int kc = ii >> 5;
            int k0 = kc * 16;
            int c0 = gg, c1 = 8 + gg;
            int ks[4] = {k0 + 2*tt, k0 + 2*tt + 1, k0 + 2*tt + 8, k0 + 2*tt + 9};
            #pragma unroll
            for (int j = 0; j < 4; j++) {
                int k = ks[j], kh = k >> 4, u = k & 15;
                va[j] = 0.25f * fw2[kh*2304 + 1536 + u*16 + c0];
                vb[j] = 0.25f * fw2[kh*2304 + 1536 + u*16 + c1];
            }
            BQ4[ii] = make_uint4(packh(va[0],va[1]), packh(va[2],va[3]),
                                 packh(vb[0],vb[1]), packh(vb[2],vb[3]));
        }
    }
    __syncthreads();

    // ---- PDL join: wait for pre_k's g_feat/g_hdup/g_ticket to be visible ----
    cudaGridDependencySynchronize();

    char*    wsb   = smem + WS_OFF + warp * WS_STRIDE;
    unsigned ws_s  = (unsigned)__cvta_generic_to_shared(wsb);
    const uint4* BGl = BG4 + lane;
    const uint4* BPl = BP4 + lane;
    const uint4* BQl = BQ4 + lane;
    const unsigned* BHu = (const unsigned*)(wsb + BH_B);

    #define STAGE_H(bufofs, e0v) do {                                            \
        const char* _src = (const char*)g_hdup + (size_t)(e0v) * 64;             \
        _Pragma("unroll")                                                        \
        for (int _it = 0; _it < 2; _it++) {                                      \
            int _idx = _it * 32 + lane;                                          \
            int _m = _idx >> 2, _j = _idx & 3;                                   \
            cpa16(ws_s + (bufofs) + HD_B + _m * 80 + _j * 16, _src + _idx * 16); \
        } } while (0)

    #define STAGE_SV(bufofs, dregv) do {                                         \
        _Pragma("unroll")                                                        \
        for (int _it = 0; _it < 5; _it++) {                                      \
            int _idx = _it * 32 + lane;                                          \
            if (_idx < 64) {                                                     \
                int _m = _idx >> 2, _j = _idx & 3;                               \
                int _d = __shfl_sync(0xFFFFFFFFu, (dregv), _m);                  \
                cpa16(ws_s + (bufofs) + S1_B + _m * 80 + _j * 16,                \
                      (const char*)g_feat + (size_t)_d * 160 + _j * 16);         \
            } else {                                                             \
                int _v = _idx - 64;                                              \
                int _m = _v / 6, _j = _v - _m * 6;                               \
                int _d = __shfl_sync(0xFFFFFFFFu, (dregv), _m);                  \
                cpa16(ws_s + (bufofs) + V1_B + _m * 112 + _j * 16,               \
                      (const char*)g_feat + (size_t)_d * 160 + 64 + _j * 16);    \
            }                                                                    \
        } } while (0)

    #define PREFIX(bufofs, eshvv) do {                                           \
        char* _nb = wsb + (bufofs);                                              \
        if (lane < 16) ((float4*)(_nb + SV_B))[lane] = (eshvv);                  \
        __syncwarp();                                                            \
        {                                                                        \
            int _m = lane >> 1, _ub = (lane & 1) * 8;                            \
            float4 _sv = ((const float4*)(_nb + SV_B))[_m];                      \
            const __half* _v1h = (const __half*)(_nb + V1_B) + _m * 56;          \
            __half* _bh = (__half*)(wsb + BH_B) + _m * 20;                       \
            _Pragma("unroll")                                                    \
            for (int _j = 0; _j < 8; _j++) {                                     \
                int _u = _ub + _j;                                               \
                float _vx = __half2float(_v1h[_u]);                              \
                float _vy = __half2float(_v1h[16 + _u]);                         \
                float _vz = __half2float(_v1h[32 + _u]);                         \
                _bh[_u] = __float2half(fmaf(_vx, _sv.y,                          \
                                       fmaf(_vy, _sv.z, _vz * _sv.w)));          \
            }                                                                    \
        }                                                                        \
        __syncwarp();                                                            \
    } while (0)

    // ---------------- bootstrap first tile (STATIC — no atomic) ----------------
    unsigned cur = (unsigned)(blockIdx.x * 16 + warp);   // < 2368 < NTILES always

    int buf = 0;
    int e0 = (int)cur * 16;
    {
        STAGE_H(0, e0);
        float4 eshv = make_float4(0.f, 0.f, 0.f, 0.f);
        int dreg = 0;
        if (lane < 16) {
            dreg = edge[N_EDGES_C + e0 + lane];
            eshv = ((const float4*)esh)[e0 + lane];
        }
        STAGE_SV(0, dreg);
        cpa_commit(); cpa_wait0(); __syncwarp();
        PREFIX(0, eshv);
    }

    // ---------------- pipelined tile loop ----------------
    for (;;) {
        const int bofs  = buf * BUF_STRIDE;
        const int nbofs = (buf ^ 1) * BUF_STRIDE;
        const char* cb  = wsb + bofs;
        const unsigned* HD0 = (const unsigned*)(cb + HD_B) + gq * 20;
        const unsigned* HD1 = (const unsigned*)(cb + HD_B) + (gq + 8) * 20;
        const unsigned* S10 = (const unsigned*)(cb + S1_B) + gq * 20;
        const unsigned* S11 = (const unsigned*)(cb + S1_B) + (gq + 8) * 20;
        const unsigned* V1u = (const unsigned*)(cb + V1_B);
        const float4*   SV  = (const float4*)(cb + SV_B);

        // ---- register-resident A operands for this tile (loaded ONCE) ----
        unsigned hA[16], hB[16];
        #pragma unroll
        for (int k = 0; k < 16; k++) { hA[k] = HD0[k]; hB[k] = HD1[k]; }
        unsigned sAr[4], sBr[4];
        sAr[0] = S10[t];     sAr[1] = S10[t + 4];
        sAr[2] = S10[8 + t]; sAr[3] = S10[12 + t];
        sBr[0] = S11[t];     sBr[1] = S11[t + 4];
        sBr[2] = S11[8 + t]; sBr[3] = S11[12 + t];

        // ---- fetch next ticket; stage h/dst/esh for it ----
        unsigned nxt;
        if (lane == 0) nxt = atomicAdd(&g_ticket, 1u);
        nxt = __shfl_sync(0xFFFFFFFFu, nxt, 0);
        const bool hn = (nxt < NTILES);
        float4 eshn = make_float4(0.f, 0.f, 0.f, 0.f);
        int dn = 0;
        if (hn) {
            int en = (int)nxt * 16;
            STAGE_H(nbofs, en);
            if (lane < 16) {
                dn   = edge[N_EDGES_C + en + lane];
                eshn = ((const float4*)esh)[en + lane];
            }
        }

        // ================ GEMM 1: g = h(x)s1, N=48 (R0|R1) ================
        float ag[6][4];
        #pragma unroll
        for (int nb = 0; nb < 6; nb++) { ag[nb][0]=0.f; ag[nb][1]=0.f; ag[nb][2]=0.f; ag[nb][3]=0.f; }

        // rotating B prefetch: bb holds kc's three blocks
        uint4 bb0 = BGl[0], bb1 = BGl[32], bb2 = BGl[64];
        #pragma unroll
        for (int kh = 0; kh < 16; kh++) {
            __half2 h0 = u2h(hA[kh]), h1 = u2h(hB[kh]);
            #pragma unroll
            for (int p = 0; p < 2; p++) {
                int kc = kh * 2 + p;
                __half2 xa = u2h(sAr[p*2+0]), xb = u2h(sAr[p*2+1]);
                __half2 ya = u2h(sBr[p*2+0]), yb = u2h(sBr[p*2+1]);
                unsigned a0 = h2u(__hmul2(h0, xa)), a1 = h2u(__hmul2(h1, ya));
                unsigned a2 = h2u(__hmul2(h0, xb)), a3 = h2u(__hmul2(h1, yb));
                mma16816(ag[0], a0, a1, a2, a3, bb0.x, bb0.y);
                mma16816(ag[1], a0, a1, a2, a3, bb0.z, bb0.w);
                mma16816(ag[2], a0, a1, a2, a3, bb1.x, bb1.y);
                mma16816(ag[3], a0, a1, a2, a3, bb1.z, bb1.w);
                mma16816(ag[4], a0, a1, a2, a3, bb2.x, bb2.y);
                mma16816(ag[5], a0, a1, a2, a3, bb2.z, bb2.w);
                if (kc < 31) {
                    bb0 = BGl[(kc+1) * 96];
                    bb1 = BGl[(kc+1) * 96 + 32];
                    bb2 = BGl[(kc+1) * 96 + 64];
                }
            }
        }

        // ---- stage dst-dependent s1/v1T for next tile ----
        if (hn) STAGE_SV(nbofs, dn);
        cpa_commit();

        // ================ GEMM 2: p = h(x)b, N=32 (R3) ================
        unsigned bAr[2], bBr[2];
        bAr[0] = BHu[gq*10 + t];       bAr[1] = BHu[gq*10 + t + 4];
        bBr[0] = BHu[(gq+8)*10 + t];   bBr[1] = BHu[(gq+8)*10 + t + 4];

        float ap[4][4];
        #pragma unroll
        for (int nb = 0; nb < 4; nb++) { ap[nb][0]=0.f; ap[nb][1]=0.f; ap[nb][2]=0.f; ap[nb][3]=0.f; }

        #pragma unroll
        for (int kc = 0; kc < 16; kc++) {
            __half2 h0 = u2h(hA[kc]), h1 = u2h(hB[kc]);
            __half2 xa = u2h(bAr[0]), xb = u2h(bAr[1]);
            __half2 ya = u2h(bBr[0]), yb = u2h(bBr[1]);
            unsigned a0 = h2u(__hmul2(h0, xa)), a1 = h2u(__hmul2(h1, ya));
            unsigned a2 = h2u(__hmul2(h0, xb)), a3 = h2u(__hmul2(h1, yb));
            #pragma unroll
            for (int p = 0; p < 2; p++) {
                uint4 bb = BPl[kc * 64 + p * 32];
                mma16816(ap[2*p],   a0, a1, a2, a3, bb.x, bb.y);
                mma16816(ap[2*p+1], a0, a1, a2, a3, bb.z, bb.w);
            }
        }

        // ---- epilogue 1: out_s = C0*s2*R0 + C3*R3 ----
        {
            float4 sv0 = SV[gq], sv1 = SV[gq + 8];
            float* row0 = out + (size_t)(e0 + gq) * 80;
            float* row1 = out + (size_t)(e0 + gq + 8) * 80;
            #pragma unroll
            for (int nb = 0; nb < 4; nb++) {
                int w = nb * 8 + 2 * t;
                float2 o0, o1;
                o0.x = fmaf(C0F * sv0.x, ag[nb][0], C3F * ap[nb][0]);
                o0.y = fmaf(C0F * sv0.x, ag[nb][1], C3F * ap[nb][1]);
                o1.x = fmaf(C0F * sv1.x, ag[nb][2], C3F * ap[nb][2]);
                o1.y = fmaf(C0F * sv1.x, ag[nb][3], C3F * ap[nb][3]);
                *(float2*)(row0 + w) = o0;
                *(float2*)(row1 + w) = o1;
            }
        }

        // ================ GEMM 3: q_i = h(x)v1_i, N=16 each (R2i) ================
        unsigned vAr[3][2], vBr[3][2];
        #pragma unroll
        for (int i = 0; i < 3; i++) {
            vAr[i][0] = V1u[gq*28 + i*8 + t];     vAr[i][1] = V1u[gq*28 + i*8 + t + 4];
            vBr[i][0] = V1u[(gq+8)*28 + i*8 + t]; vBr[i][1] = V1u[(gq+8)*28 + i*8 + t + 4];
        }

        float aq[3][2][4];
        #pragma unroll
        for (int i = 0; i < 3; i++)
            #pragma unroll
            for (int nb = 0; nb < 2; nb++) { aq[i][nb][0]=0.f; aq[i][nb][1]=0.f; aq[i][nb][2]=0.f; aq[i][nb][3]=0.f; }

        #pragma unroll
        for (int kc = 0; kc < 16; kc++) {
            __half2 h0 = u2h(hA[kc]), h1 = u2h(hB[kc]);
            uint4 bb = BQl[kc * 32];
            #pragma unroll
            for (int i = 0; i < 3; i++) {
                __half2 xa = u2h(vAr[i][0]), xb = u2h(vAr[i][1]);
                __half2 ya = u2h(vBr[i][0]), yb = u2h(vBr[i][1]);
                unsigned a0 = h2u(__hmul2(h0, xa)), a1 = h2u(__hmul2(h1, ya));
                unsigned a2 = h2u(__hmul2(h0, xb)), a3 = h2u(__hmul2(h1, yb));
                mma16816(aq[i][0], a0, a1, a2, a3, bb.x, bb.y);
                mma16816(aq[i][1], a0, a1, a2, a3, bb.z, bb.w);
            }
        }

        // ---- epilogue 2: out_v[w][i] = C1*v2[i]*R1[w] + C2*s2*R2i[w] ----
        {
            float4 sv0 = SV[gq], sv1 = SV[gq + 8];
            float* row0 = out + (size_t)(e0 + gq) * 80 + 32;
            float* row1 = out + (size_t)(e0 + gq + 8) * 80 + 32;
            #pragma unroll
            for (int nbv = 0; nbv < 2; nbv++) {
                int w = nbv * 8 + 2 * t;
                float R1a0 = ag[4 + nbv][0], R1b0 = ag[4 + nbv][1];
                float R1a1 = ag[4 + nbv][2], R1b1 = ag[4 + nbv][3];
                float v20[3] = {sv0.y, sv0.z, sv0.w};
                float v21[3] = {sv1.y, sv1.z, sv1.w};
                float o0[6], o1[6];
                #pragma unroll
                for (int i = 0; i < 3; i++) {
                    o0[i]     = fmaf(C1F * v20[i], R1a0, C2F * sv0.x * aq[i][nbv][0]);
                    o0[3 + i] = fmaf(C1F * v20[i], R1b0, C2F * sv0.x * aq[i][nbv][1]);
                    o1[i]     = fmaf(C1F * v21[i], R1a1, C2F * sv1.x * aq[i][nbv][2]);
                    o1[3 + i] = fmaf(C1F * v21[i], R1b1, C2F * sv1.x * aq[i][nbv][3]);
                }
                #pragma unroll
                for (int j = 0; j < 3; j++) {
                    *(float2*)(row0 + 3 * w + 2 * j) = make_float2(o0[2*j], o0[2*j+1]);
                    *(float2*)(row1 + 3 * w + 2 * j) = make_float2(o1[2*j], o1[2*j+1]);
                }
            }
        }

        if (!hn) break;
        // ---- retire next tile's staged data, run its short prefix ----
        cpa_wait0(); __syncwarp();
        PREFIX(nbofs, eshn);
        buf ^= 1;
        e0 = (int)nxt * 16;
    }
    #undef STAGE_H
    #undef STAGE_SV
    #undef PREFIX
}

// Host-side exact replication of the reference silu normalization constant.
static float compute_silu_c()
{
    const int N = 200001;
    const double dx = 24.0 / 200000.0;
    const double inv_sqrt_2pi = 0.3989422804014326779;
    double acc = 0.0, prev = 0.0;
    for (int i = 0; i < N; i++) {
        double x = -12.0 + dx * (double)i;
        double pdf = exp(-0.5 * x * x) * inv_sqrt_2pi;
        double s = x / (1.0 + exp(-x));
        double y = s * s * pdf;
        if (i > 0) acc += 0.5 * (y + prev) * dx;
        prev = y;
    }
    return (float)(1.0 / sqrt(acc));
}

extern "C" void kernel_launch(void* const* d_in, const int* in_sizes, int n_in,
                              void* d_out, int out_size)
{
    const float* feature = (const float*)d_in[0];
    const int*   edge    = (const int*)  d_in[1];
    const float* ele     = (const float*)d_in[2];
    const float* esh     = (const float*)d_in[3];
    const float* fw1     = (const float*)d_in[4];
    const float* fw2     = (const float*)d_in[5];
    float* out = (float*)d_out;

    float silu_c = compute_silu_c();

    cudaFuncSetAttribute(tp_mma6_kernel,
                         cudaFuncAttributeMaxDynamicSharedMemorySize, SMEM_TOTAL);

    pre_k<<<FEAT_BLOCKS + H_BLOCKS, 128>>>(feature, ele, fw1, silu_c);

    // PDL launch: main kernel starts while pre_k drains; its B-staging prologue
    // overlaps pre_k, and cudaGridDependencySynchronize() gates the tile loop.
    cudaLaunchConfig_t cfg = {};
    cfg.gridDim = dim3(GRID_C, 1, 1);
    cfg.blockDim = dim3(512, 1, 1);
    cfg.dynamicSmemBytes = SMEM_TOTAL;
    cfg.stream = 0;
    cudaLaunchAttribute attrs[1];
    attrs[0].id = cudaLaunchAttributeProgrammaticStreamSerialization;
    attrs[0].val.programmaticStreamSerializationAllowed = 1;
    cfg.attrs = attrs;
    cfg.numAttrs = 1;
    cudaError_t err = cudaLaunchKernelEx(&cfg, tp_mma6_kernel, edge, esh, fw2, out);
    if (err != cudaSuccess) {
        // Fallback: plain serialized launch (gridDepSync degenerates to no-op).
        tp_mma6_kernel<<<GRID_C, 512, SMEM_TOTAL>>>(edge, esh, fw2, out);
    }
}